// round 7
// baseline (speedup 1.0000x reference)
#include <cuda_runtime.h>
#include <cuda_fp16.h>
#include <mma.h>
#include <cstdint>

using namespace nvcuda;

#define NN   100000
#define NE   1600000

// ---------------- scratch (device globals; no allocation allowed) ----------
__device__ int    d_flag;                // 1 => edge indices stored as int64
__device__ int    d_deg[NN];             // in-degree incl self loop
__device__ float  d_dinv[NN];            // deg^-1/2
__device__ int    d_off[NN + 1];         // CSR offsets (by dst)
__device__ int    d_cur[NN];             // fill cursors
__device__ int    d_bsum[128];           // per-block scan totals
__device__ int    d_srcl[NE];            // CSR src lists
__device__ int    d_pos32[2 * NE];       // pos edge index, int32
__device__ int    d_neg32[2 * NE];       // neg edge index, int32
__device__ __half d_xh[(size_t)NN * 128];  // x fp16, later h1 fp16
__device__ __half d_g[(size_t)NN * 128];   // g1 fp16 (128w) / g2 fp16 (64w)
__device__ __half d_z[(size_t)NN * 64];    // z fp16
__device__ __half d_w1h[128 * 128];
__device__ __half d_w2h[128 * 64];

// ---------------- index width detection (1 warp) ------------------------------
__global__ void k_detect(const int* __restrict__ p) {
    int nz = 0;
    for (int i = threadIdx.x; i < 512; i += 32) nz |= p[2 * i + 1];
    for (int o = 16; o; o >>= 1) nz |= __shfl_down_sync(0xffffffffu, nz, o);
    if (threadIdx.x == 0) d_flag = (nz == 0) ? 1 : 0;
}

// ---------------- edge index -> int32 (both arrays, one pass) -----------------
__global__ void k_convidx(const int* __restrict__ pp, const int* __restrict__ np) {
    long long i = (long long)blockIdx.x * blockDim.x + threadIdx.x;
    if (i >= 4LL * NE) return;
    bool pos = (i < 2LL * NE);
    const int* p = pos ? pp : np;
    long long j = pos ? i : i - 2LL * NE;
    int v;
    if (d_flag) v = (int)((const long long*)p)[j];
    else        v = p[j];
    (pos ? d_pos32 : d_neg32)[j] = v;
}

// ---------------- fused: init_deg + weight conversion -------------------------
__global__ void k_pre(const float* __restrict__ W1, const float* __restrict__ W2) {
    int i = blockIdx.x * blockDim.x + threadIdx.x;
    if (i < NN) d_deg[i] = 1;                       // self loop
    if (i < 128 * 128) d_w1h[i] = __float2half(W1[i]);
    if (i < 128 * 64)  d_w2h[i] = __float2half(W2[i]);
}

// ---------------- x -> fp16 ---------------------------------------------------
__global__ void k_convx(const float* __restrict__ x) {
    long long i = (long long)blockIdx.x * blockDim.x + threadIdx.x;  // 8-half unit
    if (i >= (long long)NN * 128 / 8) return;
    float4 a = *(const float4*)&x[i * 8];
    float4 b = *(const float4*)&x[i * 8 + 4];
    __half2 h[4];
    h[0] = __floats2half2_rn(a.x, a.y);
    h[1] = __floats2half2_rn(a.z, a.w);
    h[2] = __floats2half2_rn(b.x, b.y);
    h[3] = __floats2half2_rn(b.z, b.w);
    *(uint4*)&d_xh[i * 8] = *(uint4*)h;
}

// ---------------- degree (int32 coalesced) -------------------------------------
__global__ void k_degree() {
    int e = blockIdx.x * blockDim.x + threadIdx.x;
    if (e >= NE) return;
    atomicAdd(&d_deg[d_pos32[NE + e]], 1);
}

// ---------------- scan phase 1: per-block scan of (deg-1) + dinv --------------
__global__ void k_scan1() {
    __shared__ int wsum[32];
    int tid = threadIdx.x, lane = tid & 31, wid = tid >> 5;
    int v = blockIdx.x * 1024 + tid;
    int deg = (v < NN) ? d_deg[v] : 1;
    if (v < NN) d_dinv[v] = rsqrtf((float)deg);
    int val = (v < NN) ? (deg - 1) : 0;
    int x = val;
    #pragma unroll
    for (int o = 1; o < 32; o <<= 1) {
        int t = __shfl_up_sync(0xffffffffu, x, o);
        if (lane >= o) x += t;
    }
    if (lane == 31) wsum[wid] = x;
    __syncthreads();
    if (wid == 0) {
        int y = wsum[lane];
        #pragma unroll
        for (int o = 1; o < 32; o <<= 1) {
            int t = __shfl_up_sync(0xffffffffu, y, o);
            if (lane >= o) y += t;
        }
        wsum[lane] = y;
    }
    __syncthreads();
    int warpoff = wid ? wsum[wid - 1] : 0;
    if (v < NN) d_off[v] = warpoff + x - val;
    if (tid == 1023) d_bsum[blockIdx.x] = wsum[31];
}

// ---------------- fused scan phases 2+3 ---------------------------------------
__global__ void k_scan23(int nblk) {
    __shared__ int sh[128];
    __shared__ int ws[4];
    int t = threadIdx.x, lane = t & 31, w = t >> 5;
    int x = 0;
    if (t < 128) {
        int val = (t < nblk) ? d_bsum[t] : 0;
        x = val;
        #pragma unroll
        for (int o = 1; o < 32; o <<= 1) {
            int tt = __shfl_up_sync(0xffffffffu, x, o);
            if (lane >= o) x += tt;
        }
        if (lane == 31) ws[w] = x;
    }
    __syncthreads();
    if (t < 128) {
        int off = 0;
        for (int q = 0; q < w; q++) off += ws[q];
        sh[t] = x + off;  // inclusive prefix of bsum
    }
    __syncthreads();
    int v = blockIdx.x * blockDim.x + t;
    if (v == 0) d_off[NN] = NE;
    if (v < NN) {
        int blk = v >> 10;
        int add = blk ? sh[blk - 1] : 0;
        int o = d_off[v] + add;
        d_off[v] = o;
        d_cur[v] = o;
    }
}

// ---------------- CSR fill (int32 coalesced) -----------------------------------
__global__ void k_fill() {
    int e = blockIdx.x * blockDim.x + threadIdx.x;
    if (e >= NE) return;
    int src = d_pos32[e];
    int dst = d_pos32[NE + e];
    int pos = atomicAdd(&d_cur[dst], 1);
    d_srcl[pos] = src;
}

// ---------------- wmma GEMM, padded smem ---------------------------------------
// BM=64 rows/block, K=128. BN=128 (8 warps) or BN=64 (4 warps). fp32 acc.
template <int BN>
__global__ void k_gemm_wmma(const __half* __restrict__ A, const __half* __restrict__ Wh,
                            __half* __restrict__ out) {
    constexpr int BM = 64, K = 128;
    constexpr int LDA = K + 8;
    constexpr int LDW = BN + 8;
    constexpr int NWARP = 4 * (BN / 64);
    constexpr int NT = NWARP * 32;
    extern __shared__ __half dyn[];
    __half* sA = dyn;                   // BM * LDA
    __half* sW = dyn + BM * LDA;        // K * LDW

    const int tid = threadIdx.x;
    const int wid = tid >> 5, lane = tid & 31;
    const int wm = wid & 3, wn = wid >> 2;
    const int rowBase = blockIdx.x * BM;

    for (int i = tid; i < BM * K / 8; i += NT) {
        int r = i >> 4;
        int c = (i & 15) * 8;
        int row = min(rowBase + r, NN - 1);
        *(uint4*)&sA[r * LDA + c] = *(const uint4*)&A[(size_t)row * K + c];
    }
    for (int i = tid; i < K * BN / 8; i += NT) {
        int r = i / (BN / 8);
        int c = (i % (BN / 8)) * 8;
        *(uint4*)&sW[r * LDW + c] = *(const uint4*)&Wh[(size_t)r * BN + c];
    }
    __syncthreads();

    wmma::fragment<wmma::accumulator, 16, 16, 16, float> c[4];
    #pragma unroll
    for (int n = 0; n < 4; n++) wmma::fill_fragment(c[n], 0.f);

    #pragma unroll
    for (int k = 0; k < K; k += 16) {
        wmma::fragment<wmma::matrix_a, 16, 16, 16, __half, wmma::row_major> a;
        wmma::load_matrix_sync(a, &sA[(wm * 16) * LDA + k], LDA);
        #pragma unroll
        for (int n = 0; n < 4; n++) {
            wmma::fragment<wmma::matrix_b, 16, 16, 16, __half, wmma::row_major> b;
            wmma::load_matrix_sync(b, &sW[k * LDW + wn * 64 + n * 16], LDW);
            wmma::mma_sync(c[n], a, b, c[n]);
        }
    }
    __syncthreads();  // done with sW; reuse as fp32 staging

    float* stage = (float*)sW + (size_t)wid * 16 * 64;  // 4KB per warp
    #pragma unroll
    for (int n = 0; n < 4; n++)
        wmma::store_matrix_sync(stage + n * 16, c[n], 64, wmma::mem_row_major);
    __syncwarp();

    for (int i = lane; i < 128; i += 32) {
        int r = i >> 3;
        int cc = (i & 7) * 8;
        int row = rowBase + wm * 16 + r;
        if (row < NN) {
            float dv = d_dinv[row];
            __half2 hv[4];
            #pragma unroll
            for (int q = 0; q < 4; q++) {
                float v0 = stage[r * 64 + cc + 2 * q] * dv;
                float v1 = stage[r * 64 + cc + 2 * q + 1] * dv;
                hv[q] = __floats2half2_rn(v0, v1);
            }
            *(uint4*)&out[(size_t)row * BN + wn * 64 + cc] = *(uint4*)hv;
        }
    }
}

// ---------------- layer-1 aggregate: warp per node, 128 cols fp16 ------------
__global__ void k_gather1(const float* __restrict__ b1) {
    int warp = (blockIdx.x * blockDim.x + threadIdx.x) >> 5;
    int lane = threadIdx.x & 31;
    if (warp >= NN) return;
    const uint2* g = (const uint2*)d_g;
    uint2 sv = g[(size_t)warp * 32 + lane];
    float2 f0 = __half22float2(*(__half2*)&sv.x);
    float2 f1 = __half22float2(*(__half2*)&sv.y);
    float4 acc = make_float4(f0.x, f0.y, f1.x, f1.y);  // self-loop term
    int s = d_off[warp], e = d_off[warp + 1];
    for (int i = s; i < e; i += 32) {
        int u = (i + lane < e) ? d_srcl[i + lane] : 0;
        int m = min(32, e - i);
        for (int j = 0; j < m; j++) {
            int uu = __shfl_sync(0xffffffffu, u, j);
            uint2 tv = g[(size_t)uu * 32 + lane];
            float2 t0 = __half22float2(*(__half2*)&tv.x);
            float2 t1 = __half22float2(*(__half2*)&tv.y);
            acc.x += t0.x; acc.y += t0.y; acc.z += t1.x; acc.w += t1.y;
        }
    }
    float dv = d_dinv[warp];
    float4 bb = ((const float4*)b1)[lane];
    __half2 h0 = __floats2half2_rn(fmaxf(dv * acc.x + bb.x, 0.f),
                                   fmaxf(dv * acc.y + bb.y, 0.f));
    __half2 h1 = __floats2half2_rn(fmaxf(dv * acc.z + bb.z, 0.f),
                                   fmaxf(dv * acc.w + bb.w, 0.f));
    uint2 o;
    o.x = *(unsigned*)&h0;
    o.y = *(unsigned*)&h1;
    ((uint2*)d_xh)[(size_t)warp * 32 + lane] = o;  // h1 fp16 over xh
}

// ---------------- layer-2 aggregate: warp per node, 64 cols fp16 -------------
__global__ void k_gather2(const float* __restrict__ b2) {
    int warp = (blockIdx.x * blockDim.x + threadIdx.x) >> 5;
    int lane = threadIdx.x & 31;
    if (warp >= NN) return;
    const unsigned* g = (const unsigned*)d_g;
    float2 acc = __half22float2(*(__half2*)&g[(size_t)warp * 32 + lane]);
    int s = d_off[warp], e = d_off[warp + 1];
    for (int i = s; i < e; i += 32) {
        int u = (i + lane < e) ? d_srcl[i + lane] : 0;
        int m = min(32, e - i);
        for (int j = 0; j < m; j++) {
            int uu = __shfl_sync(0xffffffffu, u, j);
            unsigned tv = g[(size_t)uu * 32 + lane];
            float2 t = __half22float2(*(__half2*)&tv);
            acc.x += t.x; acc.y += t.y;
        }
    }
    float dv = d_dinv[warp];
    float2 bb = ((const float2*)b2)[lane];
    __half2 zz = __floats2half2_rn(dv * acc.x + bb.x, dv * acc.y + bb.y);
    ((unsigned*)d_z)[(size_t)warp * 32 + lane] = *(unsigned*)&zz;
}

// ---------------- decoder: 2 lanes per edge, fp16 z, fp32 accumulate ---------
__global__ void k_decode(float* __restrict__ out) {
    long long gt = (long long)blockIdx.x * blockDim.x + threadIdx.x;
    long long e = gt >> 1;
    int sub = threadIdx.x & 1;
    if (e >= 2LL * NE) return;
    const int* p;
    long long ee;
    float* o;
    if (e < NE) { p = d_pos32; ee = e; o = out; }
    else        { p = d_neg32; ee = e - NE; o = out + NE; }
    int s = p[ee];
    int d = p[NE + ee];
    const uint4* z4 = (const uint4*)d_z;  // node row = 8 uint4 (64 halves)
    float pr = 0.f;
    #pragma unroll
    for (int q = 0; q < 4; q++) {
        uint4 a = z4[(size_t)s * 8 + sub * 4 + q];
        uint4 c = z4[(size_t)d * 8 + sub * 4 + q];
        const __half2* ah = reinterpret_cast<const __half2*>(&a);
        const __half2* ch = reinterpret_cast<const __half2*>(&c);
        #pragma unroll
        for (int i = 0; i < 4; i++) {
            float2 fa = __half22float2(ah[i]);
            float2 fc = __half22float2(ch[i]);
            pr += fa.x * fc.x + fa.y * fc.y;
        }
    }
    pr += __shfl_down_sync(0xffffffffu, pr, 1, 2);
    if (sub == 0) o[ee] = pr;
}

// ---------------- launch ------------------------------------------------------
extern "C" void kernel_launch(void* const* d_in, const int* in_sizes, int n_in,
                              void* d_out, int out_size) {
    const float* x   = (const float*)d_in[0];
    const int*   pos = (const int*)d_in[1];
    const int*   neg = (const int*)d_in[2];
    const float* W1  = (const float*)d_in[3];
    const float* b1  = (const float*)d_in[4];
    const float* W2  = (const float*)d_in[5];
    const float* b2  = (const float*)d_in[6];
    float* out = (float*)d_out;

    __half *xh, *g, *w1h, *w2h;
    cudaGetSymbolAddress((void**)&xh,  d_xh);
    cudaGetSymbolAddress((void**)&g,   d_g);
    cudaGetSymbolAddress((void**)&w1h, d_w1h);
    cudaGetSymbolAddress((void**)&w2h, d_w2h);

    const int smem1 = (64 * (128 + 8) + 128 * (128 + 8)) * (int)sizeof(__half);  // 52224
    const int smem2 = (64 * (128 + 8) + 128 * (64 + 8))  * (int)sizeof(__half);  // 35840
    cudaFuncSetAttribute(k_gemm_wmma<128>, cudaFuncAttributeMaxDynamicSharedMemorySize, smem1);
    cudaFuncSetAttribute(k_gemm_wmma<64>,  cudaFuncAttributeMaxDynamicSharedMemorySize, smem2);

    const int nscan = (NN + 1023) / 1024;  // 98

    cudaStream_t cap = cudaStreamPerThread;
    cudaStream_t s2;
    cudaStreamCreate(&s2);
    cudaEvent_t e0, e_idx, e_conv, e_scan, e_fill;
    cudaEventCreateWithFlags(&e0,     cudaEventDisableTiming);
    cudaEventCreateWithFlags(&e_idx,  cudaEventDisableTiming);
    cudaEventCreateWithFlags(&e_conv, cudaEventDisableTiming);
    cudaEventCreateWithFlags(&e_scan, cudaEventDisableTiming);
    cudaEventCreateWithFlags(&e_fill, cudaEventDisableTiming);

    // side stream: detect -> convidx -> convx
    cudaEventRecord(e0, cap);
    cudaStreamWaitEvent(s2, e0, 0);
    k_detect<<<1, 32, 0, s2>>>(pos);
    k_convidx<<<(unsigned)((4LL * NE + 255) / 256), 256, 0, s2>>>(pos, neg);
    cudaEventRecord(e_idx, s2);
    k_convx<<<(NN * 128 / 8 + 255) / 256, 256, 0, s2>>>(x);
    cudaEventRecord(e_conv, s2);

    // main: pre (init_deg + convw) overlaps convidx; then degree -> scans
    k_pre<<<(NN + 255) / 256, 256, 0, cap>>>(W1, W2);
    cudaStreamWaitEvent(cap, e_idx, 0);
    k_degree<<<(NE + 255) / 256, 256, 0, cap>>>();
    k_scan1<<<nscan, 1024, 0, cap>>>();
    k_scan23<<<(NN + 255) / 256, 256, 0, cap>>>(nscan);
    cudaEventRecord(e_scan, cap);

    // side: fill (atomic/L2-bound) overlaps GEMM1 (tensor-bound)
    cudaStreamWaitEvent(s2, e_scan, 0);
    k_fill<<<(NE + 255) / 256, 256, 0, s2>>>();
    cudaEventRecord(e_fill, s2);

    // main: GEMM1 g1 = dinv * (x @ W1) fp16
    cudaStreamWaitEvent(cap, e_conv, 0);
    k_gemm_wmma<128><<<(NN + 63) / 64, 256, smem1, cap>>>(xh, w1h, g);

    cudaStreamWaitEvent(cap, e_fill, 0);
    // h1 = relu(dinv*agg + b1) fp16 -> xh
    k_gather1<<<(NN * 32 + 255) / 256, 256, 0, cap>>>(b1);

    // GEMM2 + gather2
    k_gemm_wmma<64><<<(NN + 63) / 64, 128, smem2, cap>>>(xh, w2h, g);
    k_gather2<<<(NN * 32 + 255) / 256, 256, 0, cap>>>(b2);

    // decode
    long long tot = 2LL * NE * 2;
    k_decode<<<(unsigned)((tot + 255) / 256), 256, 0, cap>>>(out);

    cudaEventDestroy(e0);
    cudaEventDestroy(e_idx);
    cudaEventDestroy(e_conv);
    cudaEventDestroy(e_scan);
    cudaEventDestroy(e_fill);
    cudaStreamDestroy(s2);
}